// round 5
// baseline (speedup 1.0000x reference)
#include <cuda_runtime.h>
#include <cstdint>
#include <cstddef>

#define NTOK 8192
#define CDIM 512

// ---------------- scratch (device globals; no allocations allowed) ----------
__device__ __align__(16) float g_S1[(size_t)NTOK * NTOK];
__device__ __align__(16) float g_S2[(size_t)NTOK * NTOK];
__device__ __align__(16) float g_QK1[(size_t)NTOK * 128];
__device__ __align__(16) float g_QK2[(size_t)NTOK * 128];
__device__ __align__(16) float g_V1[(size_t)NTOK * CDIM];
__device__ __align__(16) float g_V2[(size_t)NTOK * CDIM];
__device__ __align__(16) float g_Wqk[(size_t)CDIM * 128];
__device__ __align__(16) float g_im1r[(size_t)NTOK * CDIM];
__device__ __align__(16) float g_im2r[(size_t)NTOK * CDIM];
__device__ __align__(16) float g_Wvr[(size_t)CDIM * CDIM];
__device__ __align__(16) float g_part[(size_t)2 * 64 * NTOK];
__device__ __align__(16) float g_rinv[2 * NTOK];

// ---------------- helpers ----------------------------------------------------
__device__ __forceinline__ uint32_t f2tf32(float x) {
    uint32_t r;
    asm("cvt.rna.tf32.f32 %0, %1;" : "=r"(r) : "f"(x));
    return r;
}
__device__ __forceinline__ float tf32_round(float x) { return __uint_as_float(f2tf32(x)); }

__device__ __forceinline__ void mma8(float* c, const uint32_t* a, const uint32_t* b) {
    asm volatile(
        "mma.sync.aligned.m16n8k8.row.col.f32.tf32.tf32.f32 "
        "{%0,%1,%2,%3}, {%4,%5,%6,%7}, {%8,%9}, {%0,%1,%2,%3};"
        : "+f"(c[0]), "+f"(c[1]), "+f"(c[2]), "+f"(c[3])
        : "r"(a[0]), "r"(a[1]), "r"(a[2]), "r"(a[3]), "r"(b[0]), "r"(b[1]));
}

__device__ __forceinline__ uint32_t s2u(const void* p) {
    return (uint32_t)__cvta_generic_to_shared(p);
}
__device__ __forceinline__ void cp16(uint32_t dst, const void* src) {
    asm volatile("cp.async.cg.shared.global [%0], [%1], 16;" :: "r"(dst), "l"(src) : "memory");
}

__global__ void pack_wqk(const float* __restrict__ Wq, const float* __restrict__ Wk,
                         float* __restrict__ Wqk) {
    const int i = blockIdx.x * 256 + threadIdx.x;   // 512*128
    const int r = i >> 7, c = i & 127;
    Wqk[i] = (c < 64) ? Wq[r * 64 + c] : Wk[r * 64 + (c - 64)];
}

__global__ void round_tf32(const float* __restrict__ in, float* __restrict__ out, int n4) {
    const int i = blockIdx.x * 256 + threadIdx.x;
    if (i >= n4) return;
    float4 v = ((const float4*)in)[i];
    v.x = tf32_round(v.x); v.y = tf32_round(v.y);
    v.z = tf32_round(v.z); v.w = tf32_round(v.w);
    ((float4*)out)[i] = v;
}

// ================= 3xTF32 error-compensated GEMM (Q/K projections) ===========
// 256 threads, block 128x128, warp tile 64x32. B row-major [K x N], transposed.
__global__ __launch_bounds__(256, 2)
void gemm3x(const float* __restrict__ A0, const float* __restrict__ A1, int lda,
            const float* __restrict__ B0, const float* __restrict__ B1, int ldb,
            float* __restrict__ C0, float* __restrict__ C1, int ldc, int K)
{
    constexpr int BK = 16, STR = BK + 8;
    __shared__ float As[2][128][STR];
    __shared__ float Bs[2][128][STR];

    const float* A = blockIdx.z ? A1 : A0;
    const float* B = blockIdx.z ? B1 : B0;
    float*       C = blockIdx.z ? C1 : C0;

    const int tid  = threadIdx.x;
    const int lane = tid & 31;
    const int wid  = tid >> 5;
    const int wm0  = (wid & 1) << 6;
    const int wn0  = (wid >> 1) << 5;
    const int lr   = lane >> 2;
    const int lc2  = (lane & 3) << 1;

    const size_t row0 = (size_t)blockIdx.y * 128;
    const size_t col0 = (size_t)blockIdx.x * 128;

    const int ar = tid >> 2;
    const int ac = (tid & 3) << 2;
    const float* Ap0 = A + (row0 + ar) * (size_t)lda + ac;
    const float* Ap1 = Ap0 + (size_t)64 * lda;

    const int bk_ = tid & 15;
    const int bg4 = (tid >> 4) << 2;
    const float* Bp0 = B + (size_t)bk_ * ldb + col0 + bg4;
    const float* Bp1 = Bp0 + 64;

    float4 a0 = *(const float4*)Ap0;
    float4 a1 = *(const float4*)Ap1;
    float4 b0 = *(const float4*)Bp0;
    float4 b1 = *(const float4*)Bp1;

    float acc[4][4][4];
#pragma unroll
    for (int i = 0; i < 4; i++)
#pragma unroll
        for (int j = 0; j < 4; j++)
#pragma unroll
            for (int k = 0; k < 4; k++) acc[i][j][k] = 0.f;

    auto store_tiles = [&](int bf, float4 sa0, float4 sa1, float4 sb0, float4 sb1) {
        *(float4*)&As[bf][ar][ac]      = sa0;
        *(float4*)&As[bf][ar + 64][ac] = sa1;
        Bs[bf][bg4 + 0][bk_] = sb0.x;
        Bs[bf][bg4 + 1][bk_] = sb0.y;
        Bs[bf][bg4 + 2][bk_] = sb0.z;
        Bs[bf][bg4 + 3][bk_] = sb0.w;
        Bs[bf][bg4 + 64][bk_] = sb1.x;
        Bs[bf][bg4 + 65][bk_] = sb1.y;
        Bs[bf][bg4 + 66][bk_] = sb1.z;
        Bs[bf][bg4 + 67][bk_] = sb1.w;
    };

    auto compute = [&](int bf) {
#pragma unroll
        for (int kk = 0; kk < BK; kk += 8) {
            uint32_t ah[4][4], al[4][4], bh[4][2], bl[4][2];
#pragma unroll
            for (int mt = 0; mt < 4; mt++) {
                const float2 t0 = *(const float2*)&As[bf][wm0 + mt * 16 + lr][kk + lc2];
                const float2 t1 = *(const float2*)&As[bf][wm0 + mt * 16 + lr + 8][kk + lc2];
                ah[mt][0] = f2tf32(t0.x); al[mt][0] = __float_as_uint(t0.x - __uint_as_float(ah[mt][0]));
                ah[mt][2] = f2tf32(t0.y); al[mt][2] = __float_as_uint(t0.y - __uint_as_float(ah[mt][2]));
                ah[mt][1] = f2tf32(t1.x); al[mt][1] = __float_as_uint(t1.x - __uint_as_float(ah[mt][1]));
                ah[mt][3] = f2tf32(t1.y); al[mt][3] = __float_as_uint(t1.y - __uint_as_float(ah[mt][3]));
            }
#pragma unroll
            for (int nt = 0; nt < 4; nt++) {
                const float2 t = *(const float2*)&Bs[bf][wn0 + nt * 8 + lr][kk + lc2];
                bh[nt][0] = f2tf32(t.x); bl[nt][0] = __float_as_uint(t.x - __uint_as_float(bh[nt][0]));
                bh[nt][1] = f2tf32(t.y); bl[nt][1] = __float_as_uint(t.y - __uint_as_float(bh[nt][1]));
            }
#pragma unroll
            for (int mt = 0; mt < 4; mt++)
#pragma unroll
                for (int nt = 0; nt < 4; nt++) {
                    mma8(acc[mt][nt], ah[mt], bh[nt]);
                    mma8(acc[mt][nt], al[mt], bh[nt]);
                    mma8(acc[mt][nt], ah[mt], bl[nt]);
                }
        }
    };

    store_tiles(0, a0, a1, b0, b1);
    __syncthreads();

    const int KT = K / BK;
    int buf = 0;
    for (int t = 1; t <= KT; t++) {
        if (t < KT) {
            const int ko = t * BK;
            a0 = *(const float4*)(Ap0 + ko);
            a1 = *(const float4*)(Ap1 + ko);
            b0 = *(const float4*)(Bp0 + (size_t)ko * ldb);
            b1 = *(const float4*)(Bp1 + (size_t)ko * ldb);
        }
        compute(buf);
        if (t < KT) {
            buf ^= 1;
            store_tiles(buf, a0, a1, b0, b1);
            __syncthreads();
        }
    }

#pragma unroll
    for (int mt = 0; mt < 4; mt++) {
#pragma unroll
        for (int h = 0; h < 2; h++) {
            const size_t r = row0 + wm0 + mt * 16 + lr + h * 8;
            float* Crow = C + r * (size_t)ldc + col0;
#pragma unroll
            for (int nt = 0; nt < 4; nt++) {
                const int cc = wn0 + nt * 8 + lc2;
                float2 v;
                v.x = acc[mt][nt][h * 2 + 0];
                v.y = acc[mt][nt][h * 2 + 1];
                *(float2*)(Crow + cc) = v;
            }
        }
    }
}

// ================= logits kernel: S = tf32(exp(Q @ K^T)), partial row sums ===
// 3xTF32 with hi/lo split done ONCE at staging. K=64. No max subtraction
// (|logit| <~ 60 << 88, exp cannot overflow fp32). Deterministic smem-tree
// row-sum reduction into part[z][bx][row].
__global__ __launch_bounds__(256, 2)
void logits_kernel(const float* __restrict__ QA0, const float* __restrict__ QA1,
                   const float* __restrict__ KB0, const float* __restrict__ KB1,
                   float* __restrict__ S0, float* __restrict__ S1p,
                   float* __restrict__ part)
{
    constexpr int STR = 24;
    __shared__ float Ah[128][STR], Al[128][STR], Bh[128][STR], Bl[128][STR];

    const int z = blockIdx.z;
    const float* A = z ? QA1 : QA0;
    const float* B = z ? KB1 : KB0;
    float* S = z ? S1p : S0;

    const int tid  = threadIdx.x;
    const int lane = tid & 31;
    const int wid  = tid >> 5;
    const int wm0  = (wid & 1) << 6;
    const int wn0  = (wid >> 1) << 5;
    const int lr   = lane >> 2;
    const int lc2  = (lane & 3) << 1;

    const size_t row0 = (size_t)blockIdx.y * 128;
    const size_t col0 = (size_t)blockIdx.x * 128;

    const int sr = tid >> 1;
    const int sc = (tid & 1) << 3;
    const float* Apt = A + (row0 + sr) * 128 + sc;
    const float* Bpt = B + (col0 + sr) * 128 + sc;

    float acc[4][4][4];
#pragma unroll
    for (int i = 0; i < 4; i++)
#pragma unroll
        for (int j = 0; j < 4; j++)
#pragma unroll
            for (int k = 0; k < 4; k++) acc[i][j][k] = 0.f;

    float4 ra0 = *(const float4*)Apt;
    float4 ra1 = *(const float4*)(Apt + 4);
    float4 rb0 = *(const float4*)Bpt;
    float4 rb1 = *(const float4*)(Bpt + 4);

    auto put = [&](float (*H)[STR], float (*L)[STR], int c, float v) {
        const float h = tf32_round(v);
        H[sr][c] = h;
        L[sr][c] = v - h;
    };

    for (int t = 0; t < 4; t++) {
        put(Ah, Al, sc + 0, ra0.x); put(Ah, Al, sc + 1, ra0.y);
        put(Ah, Al, sc + 2, ra0.z); put(Ah, Al, sc + 3, ra0.w);
        put(Ah, Al, sc + 4, ra1.x); put(Ah, Al, sc + 5, ra1.y);
        put(Ah, Al, sc + 6, ra1.z); put(Ah, Al, sc + 7, ra1.w);
        put(Bh, Bl, sc + 0, rb0.x); put(Bh, Bl, sc + 1, rb0.y);
        put(Bh, Bl, sc + 2, rb0.z); put(Bh, Bl, sc + 3, rb0.w);
        put(Bh, Bl, sc + 4, rb1.x); put(Bh, Bl, sc + 5, rb1.y);
        put(Bh, Bl, sc + 6, rb1.z); put(Bh, Bl, sc + 7, rb1.w);
        __syncthreads();
        if (t < 3) {
            const int ko = (t + 1) * 16;
            ra0 = *(const float4*)(Apt + ko);
            ra1 = *(const float4*)(Apt + ko + 4);
            rb0 = *(const float4*)(Bpt + ko);
            rb1 = *(const float4*)(Bpt + ko + 4);
        }
#pragma unroll
        for (int kk = 0; kk < 16; kk += 8) {
            uint32_t ah[4][4], al[4][4], bh[4][2], bl[4][2];
#pragma unroll
            for (int mt = 0; mt < 4; mt++) {
                const int r0i = wm0 + mt * 16 + lr;
                const float2 h0 = *(const float2*)&Ah[r0i][kk + lc2];
                const float2 h1 = *(const float2*)&Ah[r0i + 8][kk + lc2];
                const float2 l0 = *(const float2*)&Al[r0i][kk + lc2];
                const float2 l1 = *(const float2*)&Al[r0i + 8][kk + lc2];
                ah[mt][0] = __float_as_uint(h0.x); ah[mt][1] = __float_as_uint(h1.x);
                ah[mt][2] = __float_as_uint(h0.y); ah[mt][3] = __float_as_uint(h1.y);
                al[mt][0] = __float_as_uint(l0.x); al[mt][1] = __float_as_uint(l1.x);
                al[mt][2] = __float_as_uint(l0.y); al[mt][3] = __float_as_uint(l1.y);
            }
#pragma unroll
            for (int nt = 0; nt < 4; nt++) {
                const int nn = wn0 + nt * 8 + lr;
                const float2 h = *(const float2*)&Bh[nn][kk + lc2];
                const float2 l = *(const float2*)&Bl[nn][kk + lc2];
                bh[nt][0] = __float_as_uint(h.x); bh[nt][1] = __float_as_uint(h.y);
                bl[nt][0] = __float_as_uint(l.x); bl[nt][1] = __float_as_uint(l.y);
            }
#pragma unroll
            for (int mt = 0; mt < 4; mt++)
#pragma unroll
                for (int nt = 0; nt < 4; nt++) {
                    mma8(acc[mt][nt], ah[mt], bh[nt]);
                    mma8(acc[mt][nt], al[mt], bh[nt]);
                    mma8(acc[mt][nt], ah[mt], bl[nt]);
                }
        }
        __syncthreads();
    }

    // epilogue: exp, tf32-round, store, deterministic per-row partial sums
    float* red = &Ah[0][0];     // 4*128 floats, smem is dead now
#pragma unroll
    for (int mt = 0; mt < 4; mt++) {
#pragma unroll
        for (int h = 0; h < 2; h++) {
            const int rl = wm0 + mt * 16 + lr + 8 * h;
            float* Crow = S + (row0 + rl) * (size_t)NTOK + col0;
            float es = 0.f;
#pragma unroll
            for (int nt = 0; nt < 4; nt++) {
                const int cc = wn0 + nt * 8 + lc2;
                float2 v;
                v.x = tf32_round(__expf(acc[mt][nt][h * 2 + 0]));
                v.y = tf32_round(__expf(acc[mt][nt][h * 2 + 1]));
                es += v.x + v.y;
                *(float2*)(Crow + cc) = v;
            }
            es += __shfl_xor_sync(0xffffffffu, es, 1);
            es += __shfl_xor_sync(0xffffffffu, es, 2);
            if ((lane & 3) == 0) red[(wid >> 1) * 128 + rl] = es;
        }
    }
    __syncthreads();
    if (tid < 128) {
        const float s = red[tid] + red[128 + tid] + red[256 + tid] + red[384 + tid];
        part[((size_t)z * 64 + blockIdx.x) * NTOK + row0 + tid] = s;
    }
}

__global__ void reduce_rinv(const float* __restrict__ part, float* __restrict__ rinv) {
    const int i = blockIdx.x * 256 + threadIdx.x;   // 0..16383
    const int z = i >> 13, r = i & (NTOK - 1);
    const float* p = part + (size_t)z * 64 * NTOK + r;
    float s = 0.f;
#pragma unroll
    for (int b = 0; b < 64; b++) s += p[(size_t)b * NTOK];
    rinv[i] = 1.f / s;
}

// ================= cp.async TF32 GEMM (pure-copy staging) ====================
// 128 threads, block 128x128, warp tile 64x64. A [M x K], B [K x N] row-major.
// PV=true : C = acc * rinv[row] + Res   (PV + residual)
// PV=false: C = tf32_round(acc)         (V projection; operands pre-rounded)
template<bool PV_MODE>
__global__ __launch_bounds__(128, 2)
void gemm_cp(const float* __restrict__ A0, const float* __restrict__ A1, int lda,
             const float* __restrict__ B0, const float* __restrict__ B1, int ldb,
             const float* __restrict__ R0, const float* __restrict__ R1,
             float* __restrict__ C0, float* __restrict__ C1, int ldc, int K,
             const float* __restrict__ RI)
{
    __shared__ float As[2][128][24];
    __shared__ float Bs[2][16][132];

    const int z = blockIdx.z;
    const float* A   = z ? A1 : A0;
    const float* Bg  = z ? B1 : B0;
    const float* Res = z ? R1 : R0;
    float*       C   = z ? C1 : C0;

    const int tid  = threadIdx.x;
    const int lane = tid & 31;
    const int wid  = tid >> 5;
    const int wm0  = (wid & 1) << 6;
    const int wn0  = (wid >> 1) << 6;
    const int lr   = lane >> 2;
    const int lc2  = (lane & 3) << 1;

    const size_t row0 = (size_t)blockIdx.y * 128;
    const size_t col0 = (size_t)blockIdx.x * 128;

    const float* Ap = A + (row0 + tid) * (size_t)lda;
    const int bk = tid >> 3;
    const int bn = (tid & 7) << 4;
    const float* Bp = Bg + (size_t)bk * ldb + col0 + bn;

    float acc[4][8][4];
#pragma unroll
    for (int i = 0; i < 4; i++)
#pragma unroll
        for (int j = 0; j < 8; j++)
#pragma unroll
            for (int k = 0; k < 4; k++) acc[i][j][k] = 0.f;

    auto issue = [&](int t, int bf) {
        const float* a = Ap + (size_t)t * 16;
        const uint32_t da = s2u(&As[bf][tid][0]);
        cp16(da, a); cp16(da + 16, a + 4); cp16(da + 32, a + 8); cp16(da + 48, a + 12);
        const float* b = Bp + (size_t)t * 16 * ldb;
        const uint32_t db = s2u(&Bs[bf][bk][bn]);
        cp16(db, b); cp16(db + 16, b + 4); cp16(db + 32, b + 8); cp16(db + 48, b + 12);
        asm volatile("cp.async.commit_group;" ::: "memory");
    };

    issue(0, 0);
    const int KT = K >> 4;
    int buf = 0;
    for (int t = 0; t < KT; t++) {
        if (t + 1 < KT) {
            issue(t + 1, buf ^ 1);
            asm volatile("cp.async.wait_group 1;" ::: "memory");
        } else {
            asm volatile("cp.async.wait_group 0;" ::: "memory");
        }
        __syncthreads();
#pragma unroll
        for (int kk = 0; kk < 16; kk += 8) {
            uint32_t ah[4][4], bh[8][2];
#pragma unroll
            for (int mt = 0; mt < 4; mt++) {
                const int r0i = wm0 + mt * 16 + lr;
                const float2 t0 = *(const float2*)&As[buf][r0i][kk + lc2];
                const float2 t1 = *(const float2*)&As[buf][r0i + 8][kk + lc2];
                ah[mt][0] = __float_as_uint(t0.x);
                ah[mt][1] = __float_as_uint(t1.x);
                ah[mt][2] = __float_as_uint(t0.y);
                ah[mt][3] = __float_as_uint(t1.y);
            }
#pragma unroll
            for (int nt = 0; nt < 8; nt++) {
                const int nn = wn0 + nt * 8 + lr;
                bh[nt][0] = __float_as_uint(Bs[buf][kk + lc2][nn]);
                bh[nt][1] = __float_as_uint(Bs[buf][kk + lc2 + 1][nn]);
            }
#pragma unroll
            for (int mt = 0; mt < 4; mt++)
#pragma unroll
                for (int nt = 0; nt < 8; nt++)
                    mma8(acc[mt][nt], ah[mt], bh[nt]);
        }
        __syncthreads();
        buf ^= 1;
    }

    // epilogue
#pragma unroll
    for (int mt = 0; mt < 4; mt++) {
#pragma unroll
        for (int h = 0; h < 2; h++) {
            const size_t r = row0 + wm0 + mt * 16 + lr + h * 8;
            const float scale = PV_MODE ? RI[(size_t)z * NTOK + r] : 1.f;
            float* Crow = C + r * (size_t)ldc + col0;
            const float* Rrow = PV_MODE ? (Res + r * (size_t)ldc + col0) : nullptr;
#pragma unroll
            for (int nt = 0; nt < 8; nt++) {
                const int cc = wn0 + nt * 8 + lc2;
                float2 v;
                v.x = acc[mt][nt][h * 2 + 0];
                v.y = acc[mt][nt][h * 2 + 1];
                if (PV_MODE) {
                    const float2 rv = *(const float2*)(Rrow + cc);
                    v.x = v.x * scale + rv.x;
                    v.y = v.y * scale + rv.y;
                } else {
                    v.x = tf32_round(v.x);
                    v.y = tf32_round(v.y);
                }
                *(float2*)(Crow + cc) = v;
            }
        }
    }
}

// ---------------- launch -----------------------------------------------------
extern "C" void kernel_launch(void* const* d_in, const int* in_sizes, int n_in,
                              void* d_out, int out_size)
{
    const float* im1 = (const float*)d_in[0];
    const float* im2 = (const float*)d_in[1];
    const float* Wq  = (const float*)d_in[2];
    const float* Wk  = (const float*)d_in[3];
    const float* Wv  = (const float*)d_in[4];

    float* out1 = (float*)d_out;
    float* out2 = out1 + (size_t)NTOK * CDIM;

    float *pS1, *pS2, *pQK1, *pQK2, *pV1, *pV2, *pWqk, *pIm1r, *pIm2r, *pWvr, *pPart, *pRinv;
    cudaGetSymbolAddress((void**)&pS1,   g_S1);
    cudaGetSymbolAddress((void**)&pS2,   g_S2);
    cudaGetSymbolAddress((void**)&pQK1,  g_QK1);
    cudaGetSymbolAddress((void**)&pQK2,  g_QK2);
    cudaGetSymbolAddress((void**)&pV1,   g_V1);
    cudaGetSymbolAddress((void**)&pV2,   g_V2);
    cudaGetSymbolAddress((void**)&pWqk,  g_Wqk);
    cudaGetSymbolAddress((void**)&pIm1r, g_im1r);
    cudaGetSymbolAddress((void**)&pIm2r, g_im2r);
    cudaGetSymbolAddress((void**)&pWvr,  g_Wvr);
    cudaGetSymbolAddress((void**)&pPart, g_part);
    cudaGetSymbolAddress((void**)&pRinv, g_rinv);

    // input prep
    pack_wqk<<<256, 256>>>(Wq, Wk, pWqk);
    round_tf32<<<4096, 256>>>(im1, pIm1r, (NTOK * CDIM) / 4);
    round_tf32<<<4096, 256>>>(im2, pIm2r, (NTOK * CDIM) / 4);
    round_tf32<<<256, 256>>>(Wv, pWvr, (CDIM * CDIM) / 4);

    // Q/K projections (3xTF32, near-fp32): [Q|K]z = imz @ [Wq|Wk]
    gemm3x<<<dim3(1, 64, 2), 256>>>(im1, im2, CDIM, pWqk, pWqk, 128,
                                    pQK1, pQK2, 128, CDIM);
    // V projections (exact single-pass tf32 on pre-rounded operands)
    gemm_cp<false><<<dim3(4, 64, 2), 128>>>(pIm1r, pIm2r, CDIM, pWvr, pWvr, CDIM,
                                            nullptr, nullptr, pV1, pV2, CDIM,
                                            CDIM, nullptr);
    // logits + exp + partial row sums:  S1 = exp(Q2 K1^T),  S2 = exp(Q1 K2^T)
    logits_kernel<<<dim3(64, 64, 2), 256>>>(pQK2, pQK1, pQK1 + 64, pQK2 + 64,
                                            pS1, pS2, pPart);
    reduce_rinv<<<64, 256>>>(pPart, pRinv);
    // PV: out = (S @ V) * rinv + im   (exact mma on pre-rounded operands)
    gemm_cp<true><<<dim3(4, 64, 2), 128>>>(pS1, pS2, NTOK, pV1, pV2, CDIM,
                                           im1, im2, out1, out2, CDIM,
                                           NTOK, pRinv);
}